// round 12
// baseline (speedup 1.0000x reference)
#include <cuda_runtime.h>
#include <cstdint>

#define EPS_BN 1e-5f
typedef unsigned long long u64;

static constexpr int NSM     = 148;
static constexpr int NPIPE   = 4;      // independent 128-thread pipelines per CTA
static constexpr int NBUF    = 4;
static constexpr int STAGE_B = 8192;   // 4 rows x 2048 B
static constexpr int NPIPES_TOTAL = NSM * NPIPE;   // 592

// ---------------- smem map (bytes) ----------------
static constexpr int OFF_W    = 0;        // 192 kq * 36 u64 = 55296
static constexpr int OFF_X    = 55296;    // 4 pipes * 4 bufs * 8192 = 131072
static constexpr int OFF_PART = 186368;   // 4 * 1024 floats = 16384
static constexpr int OFF_R1   = 202752;   // 4 * 512 f = 8192
static constexpr int OFF_RES  = 210944;   // 4 * 32 f = 512
static constexpr int OFF_ROW  = 211456;   // 4 * 512 f = 8192
static constexpr int OFF_MBF  = 219648;   // 16 full mbarriers
static constexpr int OFF_MBE  = 219776;   // 16 empty mbarriers
static constexpr int OFF_T1   = 219904;
static constexpr int OFF_W2   = 219968;
static constexpr int OFF_T2   = 220224;
static constexpr int OFF_W3   = 220240;
static constexpr int OFF_B3   = 220256;
static constexpr int SMEM_BYTES = 220288;

// ---------------- helpers ----------------
__device__ __forceinline__ u64 pack2(float a, float b) {
    return ((u64)__float_as_uint(b) << 32) | (u64)__float_as_uint(a);
}
__device__ __forceinline__ void ffma2(u64& a, u64 x, u64 w) {
    asm("fma.rn.f32x2 %0, %1, %2, %0;" : "+l"(a) : "l"(x), "l"(w));
}
__device__ __forceinline__ u64 add2(u64 a, u64 b) {
    u64 r;
    asm("add.rn.f32x2 %0, %1, %2;" : "=l"(r) : "l"(a), "l"(b));
    return r;
}
__device__ __forceinline__ float hsum2(u64 a) {
    unsigned lo, hi;
    asm("mov.b64 {%0,%1}, %2;" : "=r"(lo), "=r"(hi) : "l"(a));
    return __uint_as_float(lo) + __uint_as_float(hi);
}
__device__ __forceinline__ void mbar_init(unsigned mb, unsigned cnt) {
    asm volatile("mbarrier.init.shared.b64 [%0], %1;" :: "r"(mb), "r"(cnt) : "memory");
}
// consumer wait: acquire (orders subsequent generic LDS reads)
__device__ __forceinline__ void mbar_wait_acq(unsigned mb, unsigned phase) {
    asm volatile(
        "{\n\t.reg .pred P;\n"
        "W%=:\n\t"
        "mbarrier.try_wait.parity.acquire.cta.shared::cta.b64 P, [%0], %1, 0x989680;\n\t"
        "@P bra D%=;\n\t"
        "bra W%=;\n"
        "D%=:\n\t}"
        :: "r"(mb), "r"(phase) : "memory");
}
// producer wait: relaxed (post-wait access is async-proxy TMA only)
__device__ __forceinline__ void mbar_wait_rlx(unsigned mb, unsigned phase) {
    asm volatile(
        "{\n\t.reg .pred P;\n"
        "W%=:\n\t"
        "mbarrier.try_wait.parity.relaxed.cta.shared::cta.b64 P, [%0], %1, 0x989680;\n\t"
        "@P bra D%=;\n\t"
        "bra W%=;\n"
        "D%=:\n\t}"
        :: "r"(mb), "r"(phase) : "memory");
}
__device__ __forceinline__ void mbar_arrive(unsigned mb) {
    asm volatile("mbarrier.arrive.shared.b64 _, [%0];" :: "r"(mb) : "memory");
}
__device__ __forceinline__ void barp(int id) {
    asm volatile("bar.sync %0, 128;" :: "r"(id) : "memory");
}
// one 8KB stage = 4 gmem rows of strip s
__device__ __forceinline__ void issue_stage(unsigned xs, const float* gin, int q, unsigned mb) {
    asm volatile("mbarrier.arrive.expect_tx.shared.b64 _, [%0], %1;"
                 :: "r"(mb), "r"(8192u) : "memory");
#pragma unroll
    for (int r = 0; r < 4; r++) {
        int rgg = q * 4 + r;   // 0..47
        const float* src = gin + (size_t)(rgg >> 4) * 262144 + (rgg & 15) * 512;
        asm volatile(
            "cp.async.bulk.shared::cluster.global.mbarrier::complete_tx::bytes [%0], [%1], %2, [%3];"
            :: "r"(xs + r * 2048), "l"(src), "r"(2048u), "r"(mb) : "memory");
    }
}
__device__ __forceinline__ void bulk_s2g(void* gdst, unsigned ssrc, unsigned bytes) {
    asm volatile("cp.async.bulk.global.shared::cta.bulk_group [%0], [%1], %2;"
                 :: "l"(gdst), "r"(ssrc), "r"(bytes) : "memory");
}

__global__ void __launch_bounds__(512, 1)
cnn_kernel(const float* __restrict__ in, float* __restrict__ out,
           const float* __restrict__ w1, const float* __restrict__ b1,
           const float* __restrict__ g1, const float* __restrict__ be1,
           const float* __restrict__ m1, const float* __restrict__ v1,
           const float* __restrict__ w2, const float* __restrict__ b2,
           const float* __restrict__ g2, const float* __restrict__ be2,
           const float* __restrict__ m2, const float* __restrict__ v2,
           const float* __restrict__ w3, const float* __restrict__ b3) {
    extern __shared__ char smem[];
    const unsigned sbase = (unsigned)__cvta_generic_to_shared(smem);

    const int t     = threadIdx.x;
    const int pipe  = t >> 7;          // 0..3, independent pipeline
    const int tl    = t & 127;
    const int wl    = tl >> 5;         // warp in pipe: 0..3
    const int lane  = t & 31;
    const int rgc   = wl & 1;          // row split (2)
    const int cg    = wl >> 1;         // channel group (8 ch)
    const int dxq   = lane & 3;
    const int pbase = lane >> 2;       // 0..7
    const int xoff  = pbase * 64 + dxq * 16;
    const int barid = 1 + pipe;

    u64*   wsm   = (u64*)(smem + OFF_W);
    char*  xpb   = smem + OFF_X + pipe * (NBUF * STAGE_B);
    float* part  = (float*)(smem + OFF_PART) + pipe * 1024;
    float* r1    = (float*)(smem + OFF_R1)  + pipe * 512;
    float* res   = (float*)(smem + OFF_RES) + pipe * 32;
    float* rowb  = (float*)(smem + OFF_ROW) + pipe * 512;
    float* sh_t1 = (float*)(smem + OFF_T1);
    float* sh_w2 = (float*)(smem + OFF_W2);
    float* sh_t2 = (float*)(smem + OFF_T2);
    float* sh_w3 = (float*)(smem + OFF_W3);
    float* sh_b3 = (float*)(smem + OFF_B3);
    const unsigned mbf0 = sbase + OFF_MBF + pipe * NBUF * 8;
    const unsigned mbe0 = sbase + OFF_MBE + pipe * NBUF * 8;
    const unsigned xs0  = sbase + OFF_X + pipe * (NBUF * STAGE_B);

    const int P = blockIdx.x + NSM * pipe;   // global pipe id 0..591
    int nsh = 0;
    for (int s = P; s < 1024; s += NPIPES_TOTAL) nsh++;
    const int nstages = nsh * 12;

    if (t == 0) {
#pragma unroll
        for (int i = 0; i < NPIPE * NBUF; i++) {
            mbar_init(sbase + OFF_MBF + i * 8, 1);
            mbar_init(sbase + OFF_MBE + i * 8, 4);   // one arrive per warp
        }
    }
    __syncthreads();

    // prologue: issue stages 0..2 of first strip (3-ahead steady state)
    if (tl == 0) {
        const float* gin = in + (size_t)(P >> 5) * 786432 + (size_t)(P & 31) * 8192;
#pragma unroll
        for (int g0 = 0; g0 < 3; g0++)
            if (g0 < nstages)
                issue_stage(xs0 + g0 * STAGE_B, gin, g0, mbf0 + g0 * 8);
    }

    // ---- fold BN1 into conv1 weights (hides prefetch latency) ----
#pragma unroll
    for (int j = 0; j < 6; j++) {
        int idx = j * 512 + t;          // 0..3071
        int c = idx & 15, kq = idx >> 4;
        float s1 = __ldg(g1 + c) * rsqrtf(__ldg(v1 + c) + EPS_BN);
        float4 w = *(const float4*)(w1 + c * 768 + kq * 4);
        wsm[kq * 36 + c]      = pack2(w.x * s1, w.y * s1);
        wsm[kq * 36 + 16 + c] = pack2(w.z * s1, w.w * s1);
    }
    if (t < 16) {
        float s1 = __ldg(g1 + t) * rsqrtf(__ldg(v1 + t) + EPS_BN);
        sh_t1[t] = __ldg(b1 + t) * s1 + __ldg(be1 + t) - __ldg(m1 + t) * s1;
    }
    if (t < 64) {
        int o = t >> 4;
        float s2 = __ldg(g2 + o) * rsqrtf(__ldg(v2 + o) + EPS_BN);
        sh_w2[t] = __ldg(w2 + t) * s2;
    }
    if (t < 4) {
        float s2 = __ldg(g2 + t) * rsqrtf(__ldg(v2 + t) + EPS_BN);
        sh_t2[t] = __ldg(b2 + t) * s2 + __ldg(be2 + t) - __ldg(m2 + t) * s2;
        sh_w3[t] = __ldg(w3 + t);
    }
    if (t == 0) sh_b3[0] = __ldg(b3);
    __syncthreads();   // last CTA-wide barrier; pipes now independent

    u64 acc[8][4];
#pragma unroll
    for (int c = 0; c < 8; c++)
#pragma unroll
        for (int pi = 0; pi < 4; pi++) acc[c][pi] = 0ull;

    int q = 0, sidx = 0;

    for (int g = 0; g < nstages; g++) {
        // producer: warp 0 gates buffer reuse on empty barrier, lane 0 issues (3-ahead)
        if (wl == 0) {
            int gi = g + 3;
            if (gi < nstages) {
                if (gi >= NBUF)   // buffer (gi&3) last consumed at stage gi-4
                    mbar_wait_rlx(mbe0 + (gi & 3) * 8, ((gi >> 2) - 1) & 1);
                if (lane == 0) {
                    int s = P + (gi / 12) * NPIPES_TOTAL;
                    const float* gin = in + (size_t)(s >> 5) * 786432 + (size_t)(s & 31) * 8192;
                    issue_stage(xs0 + (gi & 3) * STAGE_B, gin, gi % 12, mbf0 + (gi & 3) * 8);
                }
            }
        }

        // consumer: warps free-run; skew bounded by empty-barrier gating
        mbar_wait_acq(mbf0 + (g & 3) * 8, (g >> 2) & 1);

        const char* xb = xpb + (g & 3) * STAGE_B;

#pragma unroll
        for (int i = 0; i < 2; i++) {
            const int rgl = i * 2 + rgc;             // 0..3 local row
            const char* xp = xb + rgl * 2048 + xoff;
            ulonglong2 xv[4];
#pragma unroll
            for (int pi = 0; pi < 4; pi++)
                xv[pi] = *(const ulonglong2*)(xp + pi * 512);

            const int kqg = (q * 4 + rgl) * 4 + dxq; // 0..191
            const ulonglong2* wp = (const ulonglong2*)(wsm + kqg * 36 + cg * 8);
#pragma unroll
            for (int j = 0; j < 4; j++) {
                ulonglong2 a = wp[j];       // channels 2j,2j+1 : k = dxq*4 + 0,1
                ulonglong2 b = wp[j + 8];   // channels 2j,2j+1 : k = dxq*4 + 2,3
#pragma unroll
                for (int pi = 0; pi < 4; pi++) ffma2(acc[2 * j][pi],     xv[pi].x, a.x);
#pragma unroll
                for (int pi = 0; pi < 4; pi++) ffma2(acc[2 * j + 1][pi], xv[pi].x, a.y);
#pragma unroll
                for (int pi = 0; pi < 4; pi++) ffma2(acc[2 * j][pi],     xv[pi].y, b.x);
#pragma unroll
                for (int pi = 0; pi < 4; pi++) ffma2(acc[2 * j + 1][pi], xv[pi].y, b.y);
            }
        }

        // warp-level consumption notice: 1 arrive per warp (syncwarp orders lane reads)
        __syncwarp();
        if (lane == 0) mbar_arrive(mbe0 + (g & 3) * 8);

        // ---- strip complete: pipe-scoped reduce + epilogue + bulk store ----
        if (++q == 12) {
            const int s = P + sidx * NPIPES_TOTAL;
            q = 0; sidx++;

            // reduce dx-quad (lane bits 0-1), then hsum2 -> float partials
#pragma unroll
            for (int c = 0; c < 8; c++)
#pragma unroll
                for (int pi = 0; pi < 4; pi++) {
                    acc[c][pi] = add2(acc[c][pi], __shfl_xor_sync(0xffffffffu, acc[c][pi], 1));
                    acc[c][pi] = add2(acc[c][pi], __shfl_xor_sync(0xffffffffu, acc[c][pi], 2));
                }
            if (dxq == 0) {
#pragma unroll
                for (int c = 0; c < 8; c++)
#pragma unroll
                    for (int pi = 0; pi < 4; pi++)
                        part[rgc * 512 + (cg * 8 + c) * 32 + pi * 8 + pbase] = hsum2(acc[c][pi]);
            }
            barp(barid);

            // sum 2 rgc partials per (ch, patch), BN bias + ReLU (4 per thread)
            {
                int o0 = tl * 4;
                int chn = o0 >> 5;
                float4 a0 = *(const float4*)(part + o0);
                float4 b0 = *(const float4*)(part + 512 + o0);
                float vs[4] = {a0.x + b0.x, a0.y + b0.y, a0.z + b0.z, a0.w + b0.w};
#pragma unroll
                for (int j = 0; j < 4; j++) {
                    int p = (o0 + j) & 31;
                    r1[p * 16 + chn] = fmaxf(vs[j] + sh_t1[chn], 0.0f);
                }
            }
            barp(barid);

            // 16->4->1 funnel (warp 0 of the pipe)
            if (tl < 32) {
                float rv[16];
                const float4* rp = (const float4*)(r1 + tl * 16);
#pragma unroll
                for (int j = 0; j < 4; j++) ((float4*)rv)[j] = rp[j];
                float z0 = sh_t2[0], z1 = sh_t2[1], z2 = sh_t2[2], z3 = sh_t2[3];
#pragma unroll
                for (int c = 0; c < 16; c++) {
                    z0 = fmaf(rv[c], sh_w2[c],      z0);
                    z1 = fmaf(rv[c], sh_w2[16 + c], z1);
                    z2 = fmaf(rv[c], sh_w2[32 + c], z2);
                    z3 = fmaf(rv[c], sh_w2[48 + c], z3);
                }
                float o = sh_b3[0];
                o = fmaf(fmaxf(z0, 0.f), sh_w3[0], o);
                o = fmaf(fmaxf(z1, 0.f), sh_w3[1], o);
                o = fmaf(fmaxf(z2, 0.f), sh_w3[2], o);
                o = fmaf(fmaxf(z3, 0.f), sh_w3[3], o);
                res[tl] = o;
            }
            if (tl == 0)
                asm volatile("cp.async.bulk.wait_group.read 0;" ::: "memory");
            barp(barid);   // res visible AND prior bulk stores done reading rowb

            {
                float v = res[tl >> 2];
                ((float4*)rowb)[tl] = make_float4(v, v, v, v);
            }
            asm volatile("fence.proxy.async.shared::cta;" ::: "memory");
            barp(barid);

            if (tl == 0) {
                float* gout = out + (size_t)(s >> 5) * 262144 + (size_t)(s & 31) * 8192;
                unsigned rsrc = sbase + OFF_ROW + pipe * 2048;
#pragma unroll
                for (int row = 0; row < 16; row++)
                    bulk_s2g(gout + row * 512, rsrc, 2048u);
                asm volatile("cp.async.bulk.commit_group;" ::: "memory");
            }

#pragma unroll
            for (int c = 0; c < 8; c++)
#pragma unroll
                for (int pi = 0; pi < 4; pi++) acc[c][pi] = 0ull;
        }
    }

    if (tl == 0)
        asm volatile("cp.async.bulk.wait_group 0;" ::: "memory");
}

extern "C" void kernel_launch(void* const* d_in, const int* in_sizes, int n_in,
                              void* d_out, int out_size) {
    (void)in_sizes; (void)n_in; (void)out_size;
    cudaFuncSetAttribute(cnn_kernel, cudaFuncAttributeMaxDynamicSharedMemorySize, SMEM_BYTES);
    cnn_kernel<<<NSM, 512, SMEM_BYTES>>>(
        (const float*)d_in[0], (float*)d_out,
        (const float*)d_in[1],  (const float*)d_in[2],  (const float*)d_in[3],
        (const float*)d_in[4],  (const float*)d_in[5],  (const float*)d_in[6],
        (const float*)d_in[7],  (const float*)d_in[8],  (const float*)d_in[9],
        (const float*)d_in[10], (const float*)d_in[11], (const float*)d_in[12],
        (const float*)d_in[13], (const float*)d_in[14]);
}

// round 13
// speedup vs baseline: 1.2319x; 1.2319x over previous
#include <cuda_runtime.h>
#include <cstdint>

#define EPS_BN 1e-5f
typedef unsigned long long u64;

static constexpr int NSM     = 148;
static constexpr int NPIPE   = 8;      // independent 64-thread pipelines per CTA
static constexpr int NBUF    = 2;
static constexpr int STAGE_B = 6144;   // 3 rows x 2048 B
static constexpr int NSTAGES = 16;     // 48 rows / 3

// ---------------- smem map (bytes) ----------------
static constexpr int OFF_W    = 0;        // 192 kq * 36 u64 = 55296
static constexpr int OFF_X    = 55296;    // 8 pipes * 2 bufs * 6144 = 98304
static constexpr int OFF_R1   = 153600;   // 8 * 512 f = 16384
static constexpr int OFF_RES  = 169984;   // 8 * 32 f = 1024
static constexpr int OFF_ROW  = 171008;   // 8 * 512 f = 16384
static constexpr int OFF_MBF  = 187392;   // 8 pipes * 2 = 128
static constexpr int OFF_MBE  = 187520;   // 128
static constexpr int OFF_T1   = 187648;
static constexpr int OFF_W2   = 187712;
static constexpr int OFF_T2   = 187968;
static constexpr int OFF_W3   = 187984;
static constexpr int OFF_B3   = 188000;
static constexpr int SMEM_BYTES = 188032;

// ---------------- helpers ----------------
__device__ __forceinline__ u64 pack2(float a, float b) {
    return ((u64)__float_as_uint(b) << 32) | (u64)__float_as_uint(a);
}
__device__ __forceinline__ void ffma2(u64& a, u64 x, u64 w) {
    asm("fma.rn.f32x2 %0, %1, %2, %0;" : "+l"(a) : "l"(x), "l"(w));
}
__device__ __forceinline__ u64 add2(u64 a, u64 b) {
    u64 r;
    asm("add.rn.f32x2 %0, %1, %2;" : "=l"(r) : "l"(a), "l"(b));
    return r;
}
__device__ __forceinline__ float hsum2(u64 a) {
    unsigned lo, hi;
    asm("mov.b64 {%0,%1}, %2;" : "=r"(lo), "=r"(hi) : "l"(a));
    return __uint_as_float(lo) + __uint_as_float(hi);
}
__device__ __forceinline__ void mbar_init(unsigned mb, unsigned cnt) {
    asm volatile("mbarrier.init.shared.b64 [%0], %1;" :: "r"(mb), "r"(cnt) : "memory");
}
__device__ __forceinline__ void mbar_wait_acq(unsigned mb, unsigned phase) {
    asm volatile(
        "{\n\t.reg .pred P;\n"
        "W%=:\n\t"
        "mbarrier.try_wait.parity.acquire.cta.shared::cta.b64 P, [%0], %1, 0x989680;\n\t"
        "@P bra D%=;\n\t"
        "bra W%=;\n"
        "D%=:\n\t}"
        :: "r"(mb), "r"(phase) : "memory");
}
__device__ __forceinline__ void mbar_wait_rlx(unsigned mb, unsigned phase) {
    asm volatile(
        "{\n\t.reg .pred P;\n"
        "W%=:\n\t"
        "mbarrier.try_wait.parity.relaxed.cta.shared::cta.b64 P, [%0], %1, 0x989680;\n\t"
        "@P bra D%=;\n\t"
        "bra W%=;\n"
        "D%=:\n\t}"
        :: "r"(mb), "r"(phase) : "memory");
}
__device__ __forceinline__ void mbar_arrive(unsigned mb) {
    asm volatile("mbarrier.arrive.shared.b64 _, [%0];" :: "r"(mb) : "memory");
}
__device__ __forceinline__ void barp(int id) {
    asm volatile("bar.sync %0, 64;" :: "r"(id) : "memory");
}
// one 6KB stage = 3 gmem rows of the strip
__device__ __forceinline__ void issue_stage(unsigned xs, const float* gin, int q, unsigned mb) {
    asm volatile("mbarrier.arrive.expect_tx.shared.b64 _, [%0], %1;"
                 :: "r"(mb), "r"(6144u) : "memory");
#pragma unroll
    for (int r = 0; r < 3; r++) {
        int rgg = q * 3 + r;   // 0..47
        const float* src = gin + (size_t)(rgg >> 4) * 262144 + (rgg & 15) * 512;
        asm volatile(
            "cp.async.bulk.shared::cluster.global.mbarrier::complete_tx::bytes [%0], [%1], %2, [%3];"
            :: "r"(xs + r * 2048), "l"(src), "r"(2048u), "r"(mb) : "memory");
    }
}
__device__ __forceinline__ void bulk_s2g(void* gdst, unsigned ssrc, unsigned bytes) {
    asm volatile("cp.async.bulk.global.shared::cta.bulk_group [%0], [%1], %2;"
                 :: "l"(gdst), "r"(ssrc), "r"(bytes) : "memory");
}

__global__ void __launch_bounds__(512, 1)
cnn_kernel(const float* __restrict__ in, float* __restrict__ out,
           const float* __restrict__ w1, const float* __restrict__ b1,
           const float* __restrict__ g1, const float* __restrict__ be1,
           const float* __restrict__ m1, const float* __restrict__ v1,
           const float* __restrict__ w2, const float* __restrict__ b2,
           const float* __restrict__ g2, const float* __restrict__ be2,
           const float* __restrict__ m2, const float* __restrict__ v2,
           const float* __restrict__ w3, const float* __restrict__ b3) {
    extern __shared__ char smem[];
    const unsigned sbase = (unsigned)__cvta_generic_to_shared(smem);

    const int t     = threadIdx.x;
    const int pipe  = t >> 6;          // 0..7, independent 64-thread pipeline
    const int tl    = t & 63;
    const int cg    = tl >> 5;         // warp in pipe = channel group (8 ch)
    const int lane  = t & 31;
    const int dxq   = lane & 3;
    const int pbase = lane >> 2;       // 0..7
    const int xoff  = pbase * 64 + dxq * 16;
    const int barid = 1 + pipe;

    u64*   wsm   = (u64*)(smem + OFF_W);
    float* r1    = (float*)(smem + OFF_R1)  + pipe * 512;
    float* res   = (float*)(smem + OFF_RES) + pipe * 32;
    float* rowb  = (float*)(smem + OFF_ROW) + pipe * 512;
    float* sh_t1 = (float*)(smem + OFF_T1);
    float* sh_w2 = (float*)(smem + OFF_W2);
    float* sh_t2 = (float*)(smem + OFF_T2);
    float* sh_w3 = (float*)(smem + OFF_W3);
    float* sh_b3 = (float*)(smem + OFF_B3);
    char*  xpb   = smem + OFF_X + pipe * (NBUF * STAGE_B);
    const unsigned mbf0 = sbase + OFF_MBF + pipe * NBUF * 8;
    const unsigned mbe0 = sbase + OFF_MBE + pipe * NBUF * 8;
    const unsigned xs0  = sbase + OFF_X + pipe * (NBUF * STAGE_B);

    const int P = blockIdx.x + NSM * pipe;   // strip id; 1184 pipes >= 1024 strips
    const bool active = (P < 1024);

    if (t == 0) {
#pragma unroll
        for (int i = 0; i < NPIPE * NBUF; i++) {
            mbar_init(sbase + OFF_MBF + i * 8, 1);
            mbar_init(sbase + OFF_MBE + i * 8, 2);   // one arrive per warp
        }
    }
    __syncthreads();

    const float* gin = in + (size_t)(P >> 5) * 786432 + (size_t)(P & 31) * 8192;
    if (active && tl == 0)
        issue_stage(xs0, gin, 0, mbf0);   // prologue: stage 0 into buf 0

    // ---- fold BN1 into conv1 weights (hides prefetch latency) ----
#pragma unroll
    for (int j = 0; j < 6; j++) {
        int idx = j * 512 + t;          // 0..3071
        int c = idx & 15, kq = idx >> 4;
        float s1 = __ldg(g1 + c) * rsqrtf(__ldg(v1 + c) + EPS_BN);
        float4 w = *(const float4*)(w1 + c * 768 + kq * 4);
        wsm[kq * 36 + c]      = pack2(w.x * s1, w.y * s1);
        wsm[kq * 36 + 16 + c] = pack2(w.z * s1, w.w * s1);
    }
    if (t < 16) {
        float s1 = __ldg(g1 + t) * rsqrtf(__ldg(v1 + t) + EPS_BN);
        sh_t1[t] = __ldg(b1 + t) * s1 + __ldg(be1 + t) - __ldg(m1 + t) * s1;
    }
    if (t < 64) {
        int o = t >> 4;
        float s2 = __ldg(g2 + o) * rsqrtf(__ldg(v2 + o) + EPS_BN);
        sh_w2[t] = __ldg(w2 + t) * s2;
    }
    if (t < 4) {
        float s2 = __ldg(g2 + t) * rsqrtf(__ldg(v2 + t) + EPS_BN);
        sh_t2[t] = __ldg(b2 + t) * s2 + __ldg(be2 + t) - __ldg(m2 + t) * s2;
        sh_w3[t] = __ldg(w3 + t);
    }
    if (t == 0) sh_b3[0] = __ldg(b3);
    __syncthreads();   // last CTA-wide barrier; pipes now independent

    if (!active) return;   // idle pipes exit (after both CTA-wide barriers)

    // acc[c][pi]: channels cg*8+c, patch pi*8+pbase, k-pair packed (complete
    // per-warp conv sums — no cross-warp reduction needed: warp = all rows)
    u64 acc[8][4];
#pragma unroll
    for (int c = 0; c < 8; c++)
#pragma unroll
        for (int pi = 0; pi < 4; pi++) acc[c][pi] = 0ull;

    for (int g = 0; g < NSTAGES; g++) {
        // producer: warp 0 gates reuse on empty barrier; lane 0 issues (1-ahead)
        if (cg == 0) {
            int gi = g + 1;
            if (gi < NSTAGES) {
                if (gi >= NBUF)
                    mbar_wait_rlx(mbe0 + (gi & 1) * 8, ((gi >> 1) - 1) & 1);
                if (lane == 0)
                    issue_stage(xs0 + (gi & 1) * STAGE_B, gin, gi, mbf0 + (gi & 1) * 8);
            }
        }

        mbar_wait_acq(mbf0 + (g & 1) * 8, (g >> 1) & 1);

        const char* xb = xpb + (g & 1) * STAGE_B;

#pragma unroll
        for (int r = 0; r < 3; r++) {
            const char* xp = xb + r * 2048 + xoff;
            ulonglong2 xv[4];
#pragma unroll
            for (int pi = 0; pi < 4; pi++)
                xv[pi] = *(const ulonglong2*)(xp + pi * 512);

            const int kqg = (g * 3 + r) * 4 + dxq;   // 0..191
            const ulonglong2* wp = (const ulonglong2*)(wsm + kqg * 36 + cg * 8);
#pragma unroll
            for (int j = 0; j < 4; j++) {
                ulonglong2 a = wp[j];       // ch 2j,2j+1 : k = dxq*4 + 0,1
                ulonglong2 b = wp[j + 8];   // ch 2j,2j+1 : k = dxq*4 + 2,3
#pragma unroll
                for (int pi = 0; pi < 4; pi++) ffma2(acc[2 * j][pi],     xv[pi].x, a.x);
#pragma unroll
                for (int pi = 0; pi < 4; pi++) ffma2(acc[2 * j + 1][pi], xv[pi].x, a.y);
#pragma unroll
                for (int pi = 0; pi < 4; pi++) ffma2(acc[2 * j][pi],     xv[pi].y, b.x);
#pragma unroll
                for (int pi = 0; pi < 4; pi++) ffma2(acc[2 * j + 1][pi], xv[pi].y, b.y);
            }
        }

        __syncwarp();
        if (lane == 0) mbar_arrive(mbe0 + (g & 1) * 8);
    }

    // ---- epilogue (once per pipe): dx-quad reduce -> BN+ReLU -> funnel -> store ----
#pragma unroll
    for (int c = 0; c < 8; c++)
#pragma unroll
        for (int pi = 0; pi < 4; pi++) {
            acc[c][pi] = add2(acc[c][pi], __shfl_xor_sync(0xffffffffu, acc[c][pi], 1));
            acc[c][pi] = add2(acc[c][pi], __shfl_xor_sync(0xffffffffu, acc[c][pi], 2));
        }
    if (dxq == 0) {
#pragma unroll
        for (int c = 0; c < 8; c++) {
            int chn = cg * 8 + c;
            float tb = sh_t1[chn];
#pragma unroll
            for (int pi = 0; pi < 4; pi++)
                r1[(pi * 8 + pbase) * 16 + chn] = fmaxf(hsum2(acc[c][pi]) + tb, 0.0f);
        }
    }
    barp(barid);

    // 16->4->1 funnel (warp 0 of the pipe; lane = patch)
    if (tl < 32) {
        float rv[16];
        const float4* rp = (const float4*)(r1 + tl * 16);
#pragma unroll
        for (int j = 0; j < 4; j++) ((float4*)rv)[j] = rp[j];
        float z0 = sh_t2[0], z1 = sh_t2[1], z2 = sh_t2[2], z3 = sh_t2[3];
#pragma unroll
        for (int c = 0; c < 16; c++) {
            z0 = fmaf(rv[c], sh_w2[c],      z0);
            z1 = fmaf(rv[c], sh_w2[16 + c], z1);
            z2 = fmaf(rv[c], sh_w2[32 + c], z2);
            z3 = fmaf(rv[c], sh_w2[48 + c], z3);
        }
        float o = sh_b3[0];
        o = fmaf(fmaxf(z0, 0.f), sh_w3[0], o);
        o = fmaf(fmaxf(z1, 0.f), sh_w3[1], o);
        o = fmaf(fmaxf(z2, 0.f), sh_w3[2], o);
        o = fmaf(fmaxf(z3, 0.f), sh_w3[3], o);
        res[tl] = o;
    }
    barp(barid);

    // build one upsampled 2KB row; 64 threads x 2 float4
#pragma unroll
    for (int i = 0; i < 2; i++) {
        int idx = i * 64 + tl;            // 0..127
        float v = res[idx >> 2];
        ((float4*)rowb)[idx] = make_float4(v, v, v, v);
    }
    asm volatile("fence.proxy.async.shared::cta;" ::: "memory");
    barp(barid);

    if (tl == 0) {
        float* gout = out + (size_t)(P >> 5) * 262144 + (size_t)(P & 31) * 8192;
        unsigned rsrc = sbase + OFF_ROW + pipe * 2048;
#pragma unroll
        for (int row = 0; row < 16; row++)
            bulk_s2g(gout + row * 512, rsrc, 2048u);
        asm volatile("cp.async.bulk.commit_group;" ::: "memory");
        asm volatile("cp.async.bulk.wait_group 0;" ::: "memory");
    }
}

extern "C" void kernel_launch(void* const* d_in, const int* in_sizes, int n_in,
                              void* d_out, int out_size) {
    (void)in_sizes; (void)n_in; (void)out_size;
    cudaFuncSetAttribute(cnn_kernel, cudaFuncAttributeMaxDynamicSharedMemorySize, SMEM_BYTES);
    cnn_kernel<<<NSM, 512, SMEM_BYTES>>>(
        (const float*)d_in[0], (float*)d_out,
        (const float*)d_in[1],  (const float*)d_in[2],  (const float*)d_in[3],
        (const float*)d_in[4],  (const float*)d_in[5],  (const float*)d_in[6],
        (const float*)d_in[7],  (const float*)d_in[8],  (const float*)d_in[9],
        (const float*)d_in[10], (const float*)d_in[11], (const float*)d_in[12],
        (const float*)d_in[13], (const float*)d_in[14]);
}